// round 6
// baseline (speedup 1.0000x reference)
#include <cuda_runtime.h>
#include <cstdint>

// Problem constants
#define HW_     16384            // H*W = 128*128
#define CHW_    4194304          // C*H*W = 256*16384
#define NB_     8                // batch
#define JD_     32768            // C*H*W / W = 32768 (reshaped inner dim)
#define SPLITK_ 128              // split-K factor for logit GEMM
#define KCH_    256              // 32768 / 128

// Output chunk offsets (floats) for the concatenated tuple
// (out_w, x_Qw, x_Kw, x_Vw, gamma, att)
#define OFF_OUTW  0
#define OFF_QW    33554432
#define OFF_KW    67108864
#define OFF_VW    100663296
#define OFF_GAMMA 134217728
#define OFF_ATT   134217729
#define FULL_SIZE 134348801

// ---------------- device-global scratch (no allocations allowed) -----------
__device__ float g_kscr[(size_t)NB_ * CHW_];             // K conv, normal layout
__device__ float g_vscr[(size_t)NB_ * CHW_];             // V conv, normal layout
__device__ float g_psum[(size_t)NB_ * SPLITK_ * 16384];  // split-K partial logits
__device__ float g_att [(size_t)NB_ * 16384];            // softmax result (aligned)
// fallback buffers in case d_out only holds out_w
__device__ float g_qfb [(size_t)NB_ * CHW_];
__device__ float g_ktfb[(size_t)NB_ * CHW_];
__device__ float g_vtfb[(size_t)NB_ * CHW_];

// ---------------- packed f32x2 helpers (baseline PTX, sm_100+) -------------
typedef unsigned long long u64t;

__device__ __forceinline__ u64t dup2(float a) {
    u64t r; asm("mov.b64 %0, {%1, %1};" : "=l"(r) : "f"(a)); return r;
}
__device__ __forceinline__ u64t pack2(float x, float y) {
    u64t r; asm("mov.b64 %0, {%1, %2};" : "=l"(r) : "f"(x), "f"(y)); return r;
}
__device__ __forceinline__ void unpack2(u64t v, float& x, float& y) {
    asm("mov.b64 {%0, %1}, %2;" : "=f"(x), "=f"(y) : "l"(v));
}
__device__ __forceinline__ void ffma2(u64t& d, u64t a, u64t b) {
    asm("fma.rn.f32x2 %0, %1, %2, %0;" : "+l"(d) : "l"(a), "l"(b));
}

// ---------------- 128x128x16 double-buffered fp32x2 SGEMM core -------------
// A: row-major, tile rows [0,128) of passed pointer, lda given
// B: row-major, tile cols [0,128) of passed pointer, ldb given
// K multiple of 16. 256 threads. smem: sA/sB each 2*2048 floats.
// Accumulator: acc2[i][j2] = packed (j=2*j2, j=2*j2+1) pair, via fma.rn.f32x2.
__device__ __forceinline__ void sgemm_block_core(
    const float* __restrict__ A, int lda,
    const float* __restrict__ B, int ldb,
    int K, u64t acc2[8][4], float* sA, float* sB)
{
    const int tid  = threadIdx.x;
    const int aRow = tid >> 2;          // 0..63  (and +64)
    const int aCol = (tid & 3) << 2;    // 0,4,8,12
    const int bRow = tid >> 5;          // 0..7   (and +8)
    const int bCol = (tid & 31) << 2;   // 0..124
    const int nT   = K >> 4;

    float4 ra0, ra1, rb0, rb1;

    // prologue: tile 0 -> buffer 0
    ra0 = *(const float4*)(A + (size_t)aRow      * lda + aCol);
    ra1 = *(const float4*)(A + (size_t)(aRow+64) * lda + aCol);
    rb0 = *(const float4*)(B + (size_t)bRow      * ldb + bCol);
    rb1 = *(const float4*)(B + (size_t)(bRow+8)  * ldb + bCol);
    {
        float* s = sA;
        s[(aCol+0)*128 + aRow]    = ra0.x;
        s[(aCol+1)*128 + aRow]    = ra0.y;
        s[(aCol+2)*128 + aRow]    = ra0.z;
        s[(aCol+3)*128 + aRow]    = ra0.w;
        s[(aCol+0)*128 + aRow+64] = ra1.x;
        s[(aCol+1)*128 + aRow+64] = ra1.y;
        s[(aCol+2)*128 + aRow+64] = ra1.z;
        s[(aCol+3)*128 + aRow+64] = ra1.w;
        *(float4*)(sB + bRow*128     + bCol) = rb0;
        *(float4*)(sB + (bRow+8)*128 + bCol) = rb1;
    }
    __syncthreads();

    const int tx = tid & 15, ty = tid >> 4;

    for (int kt = 0; kt < nT; kt++) {
        if (kt + 1 < nT) {
            const float* Ak = A + ((kt + 1) << 4);
            const float* Bk = B + (size_t)((kt + 1) << 4) * ldb;
            ra0 = *(const float4*)(Ak + (size_t)aRow      * lda + aCol);
            ra1 = *(const float4*)(Ak + (size_t)(aRow+64) * lda + aCol);
            rb0 = *(const float4*)(Bk + (size_t)bRow      * ldb + bCol);
            rb1 = *(const float4*)(Bk + (size_t)(bRow+8)  * ldb + bCol);
        }
        const float* cA = sA + (kt & 1) * 2048;
        const float* cB = sB + (kt & 1) * 2048;
        #pragma unroll
        for (int kk = 0; kk < 16; kk++) {
            float4 a0 = *(const float4*)(cA + kk*128 + ty*8);
            float4 a1 = *(const float4*)(cA + kk*128 + ty*8 + 4);
            float4 b0 = *(const float4*)(cB + kk*128 + tx*8);
            float4 b1 = *(const float4*)(cB + kk*128 + tx*8 + 4);
            u64t bb0 = pack2(b0.x, b0.y);
            u64t bb1 = pack2(b0.z, b0.w);
            u64t bb2 = pack2(b1.x, b1.y);
            u64t bb3 = pack2(b1.z, b1.w);
            float av[8] = {a0.x,a0.y,a0.z,a0.w,a1.x,a1.y,a1.z,a1.w};
            #pragma unroll
            for (int i = 0; i < 8; i++) {
                u64t ad = dup2(av[i]);
                ffma2(acc2[i][0], ad, bb0);
                ffma2(acc2[i][1], ad, bb1);
                ffma2(acc2[i][2], ad, bb2);
                ffma2(acc2[i][3], ad, bb3);
            }
        }
        if (kt + 1 < nT) {
            float* s = sA + ((kt + 1) & 1) * 2048;
            s[(aCol+0)*128 + aRow]    = ra0.x;
            s[(aCol+1)*128 + aRow]    = ra0.y;
            s[(aCol+2)*128 + aRow]    = ra0.z;
            s[(aCol+3)*128 + aRow]    = ra0.w;
            s[(aCol+0)*128 + aRow+64] = ra1.x;
            s[(aCol+1)*128 + aRow+64] = ra1.y;
            s[(aCol+2)*128 + aRow+64] = ra1.z;
            s[(aCol+3)*128 + aRow+64] = ra1.w;
            float* sb2 = sB + ((kt + 1) & 1) * 2048;
            *(float4*)(sb2 + bRow*128     + bCol) = rb0;
            *(float4*)(sb2 + (bRow+8)*128 + bCol) = rb1;
            __syncthreads();
        }
    }
}

#define ACC_INIT(acc2)                                        \
    u64t acc2[8][4];                                          \
    _Pragma("unroll")                                         \
    for (int _i = 0; _i < 8; _i++)                            \
        _Pragma("unroll")                                     \
        for (int _j = 0; _j < 4; _j++) acc2[_i][_j] = 0ull;

#define ACC_UNPACK(acc2, acc)                                 \
    float acc[8][8];                                          \
    _Pragma("unroll")                                         \
    for (int _i = 0; _i < 8; _i++)                            \
        _Pragma("unroll")                                     \
        for (int _j = 0; _j < 4; _j++)                        \
            unpack2(acc2[_i][_j], acc[_i][2*_j], acc[_i][2*_j+1]);

// ---------------- kernel 1: fused QKV 1x1 conv + bias + ReLU ---------------
// grid (128, 6, 8): x = n-tile, y = (m-tile | op*2), z = batch
__global__ __launch_bounds__(256, 2) void conv_qkv_kernel(
    const float* __restrict__ x,
    const float* __restrict__ Wq, const float* __restrict__ bq,
    const float* __restrict__ Wk, const float* __restrict__ bk,
    const float* __restrict__ Wv, const float* __restrict__ bv,
    float* __restrict__ qdst)
{
    __shared__ float smem[8192];
    if (!qdst) qdst = g_qfb;
    const int b  = blockIdx.z;
    const int op = blockIdx.y >> 1;
    const int m0 = (blockIdx.y & 1) << 7;
    const int n0 = blockIdx.x << 7;

    const float* Wsel = (op == 0) ? Wq : (op == 1) ? Wk : Wv;
    const float* bsel = (op == 0) ? bq : (op == 1) ? bk : bv;
    float*       dst  = (op == 0) ? qdst : (op == 1) ? g_kscr : g_vscr;

    const float* A = Wsel + (size_t)m0 * 256;
    const float* B = x + (size_t)b * CHW_ + n0;
    dst += (size_t)b * CHW_;

    ACC_INIT(acc2);
    sgemm_block_core(A, 256, B, HW_, 256, acc2, smem, smem + 4096);
    ACC_UNPACK(acc2, acc);

    const int tx = threadIdx.x & 15, ty = threadIdx.x >> 4;
    #pragma unroll
    for (int i = 0; i < 8; i++) {
        const int m = m0 + ty * 8 + i;
        const float bb = __ldg(bsel + m);
        float* row = dst + (size_t)m * HW_ + n0 + tx * 8;
        float4 v0, v1;
        v0.x = fmaxf(acc[i][0] + bb, 0.f);
        v0.y = fmaxf(acc[i][1] + bb, 0.f);
        v0.z = fmaxf(acc[i][2] + bb, 0.f);
        v0.w = fmaxf(acc[i][3] + bb, 0.f);
        v1.x = fmaxf(acc[i][4] + bb, 0.f);
        v1.y = fmaxf(acc[i][5] + bb, 0.f);
        v1.z = fmaxf(acc[i][6] + bb, 0.f);
        v1.w = fmaxf(acc[i][7] + bb, 0.f);
        *(float4*)row       = v0;
        *(float4*)(row + 4) = v1;
    }
}

// ---------------- kernel 2: K/V layout transpose into x_Kw / x_Vw ----------
// in:  scr[b][c][p]   out: [b][j][i] with j = (c&1)*16384 + p, i = c>>1
// grid (512, 4, 32): x = p-tile, y = i-tile, z = (b<<2)|(par<<1)|kv
__global__ void transpose_kv_kernel(float* __restrict__ ktw, float* __restrict__ vtw)
{
    __shared__ float tile[32][33];
    if (!ktw) ktw = g_ktfb;
    if (!vtw) vtw = g_vtfb;
    const int z   = blockIdx.z;
    const int kv  = z & 1;
    const int par = (z >> 1) & 1;
    const int b   = z >> 2;
    const float* src = (kv ? g_vscr : g_kscr) + (size_t)b * CHW_;
    float*       dst = (kv ? vtw    : ktw   ) + (size_t)b * CHW_;
    const int p0 = blockIdx.x << 5, i0 = blockIdx.y << 5;
    const int tx = threadIdx.x, ty = threadIdx.y;
    #pragma unroll
    for (int r = 0; r < 4; r++) {
        const int ii = ty + r * 8;
        tile[ii][tx] = src[(size_t)(2 * (i0 + ii) + par) * HW_ + p0 + tx];
    }
    __syncthreads();
    #pragma unroll
    for (int r = 0; r < 4; r++) {
        const int pp = ty + r * 8;
        dst[(size_t)(par * 16384 + p0 + pp) * 128 + i0 + tx] = tile[tx][pp];
    }
}

// ---------------- kernel 3: split-K logit GEMM  att_raw = Qr * Kr^T --------
// grid (SPLITK_, 8): x = k-split s, y = batch. Partial [128x128] -> g_psum.
__global__ __launch_bounds__(256, 2) void att_gemm_kernel(
    const float* __restrict__ q, const float* __restrict__ kt)
{
    __shared__ float smem[8192];
    if (!q)  q  = g_qfb;
    if (!kt) kt = g_ktfb;
    const int s = blockIdx.x, b = blockIdx.y;
    const float* A = q  + (size_t)b * CHW_ + (size_t)s * KCH_;        // lda = 32768
    const float* B = kt + (size_t)b * CHW_ + (size_t)s * KCH_ * 128;  // ldb = 128

    ACC_INIT(acc2);
    sgemm_block_core(A, JD_, B, 128, KCH_, acc2, smem, smem + 4096);
    ACC_UNPACK(acc2, acc);

    float* Cp = g_psum + ((size_t)b * SPLITK_ + s) * 16384;
    const int tx = threadIdx.x & 15, ty = threadIdx.x >> 4;
    #pragma unroll
    for (int i = 0; i < 8; i++) {
        float* row = Cp + (size_t)(ty * 8 + i) * 128 + tx * 8;
        float4 v0 = {acc[i][0], acc[i][1], acc[i][2], acc[i][3]};
        float4 v1 = {acc[i][4], acc[i][5], acc[i][6], acc[i][7]};
        *(float4*)row       = v0;
        *(float4*)(row + 4) = v1;
    }
}

// ---------------- kernel 4: Kahan split-K reduce + softmax over axis=1 -----
// Coalesced layout: warp lanes span 32 consecutive ip columns; each thread
// Kahan-reduces 16 rows (i) over all 128 split-K slices.
// grid (4, 8): x = ip-tile (32 cols), y = batch; 256 threads = 8 warps.
__global__ __launch_bounds__(256) void softmax_kernel(
    float* __restrict__ attw, float* __restrict__ gmw,
    const float* __restrict__ gamma)
{
    __shared__ float sm[128 * 33];
    __shared__ float smx[32], sZ[32];
    const int b    = blockIdx.y;
    const int lane = threadIdx.x & 31;
    const int w    = threadIdx.x >> 5;
    const int ip   = (blockIdx.x << 5) + lane;

    const float* base = g_psum + (size_t)b * SPLITK_ * 16384
                      + (size_t)(w * 16) * 128 + ip;

    float s[16], c[16];
    #pragma unroll
    for (int r = 0; r < 16; r++) { s[r] = 0.f; c[r] = 0.f; }

    for (int t = 0; t < SPLITK_; t++) {
        const float* p = base + (size_t)t * 16384;
        #pragma unroll
        for (int r = 0; r < 16; r++) {
            float v = p[r * 128];
            float y = __fsub_rn(v, c[r]);
            float u = __fadd_rn(s[r], y);
            c[r] = __fsub_rn(__fsub_rn(u, s[r]), y);
            s[r] = u;
        }
    }

    #pragma unroll
    for (int r = 0; r < 16; r++) sm[(w * 16 + r) * 33 + lane] = s[r];
    __syncthreads();

    if (w == 0) {
        float m = -3.4e38f;
        for (int i = 0; i < 128; i++) m = fmaxf(m, sm[i * 33 + lane]);
        smx[lane] = m;
    }
    __syncthreads();

    const float mx = smx[lane];
    float e[16];
    #pragma unroll
    for (int r = 0; r < 16; r++) {
        e[r] = expf(s[r] - mx);
        sm[(w * 16 + r) * 33 + lane] = e[r];
    }
    __syncthreads();

    if (w == 0) {
        float z = 0.f;
        for (int i = 0; i < 128; i++) z += sm[i * 33 + lane];
        sZ[lane] = z;
    }
    __syncthreads();

    const float zi = 1.f / sZ[lane];
    float* ga = g_att + (size_t)b * 16384 + ip;
    #pragma unroll
    for (int r = 0; r < 16; r++) {
        const int i = w * 16 + r;
        const float rr = e[r] * zi;
        ga[(size_t)i * 128] = rr;
        if (attw) attw[(size_t)b * 16384 + (size_t)i * 128 + ip] = rr;
    }
    if (gmw && b == 0 && blockIdx.x == 0 && threadIdx.x == 0) *gmw = __ldg(gamma);
}

// ---------------- kernel 5: out1 = x_Vw @ att, scaled by gamma -------------
// grid (256, 8): x = m-tile (of 32768), y = batch
__global__ __launch_bounds__(256, 2) void out_gemm_kernel(
    const float* __restrict__ vt, float* __restrict__ outw,
    const float* __restrict__ gamma)
{
    __shared__ float smem[8192];
    if (!vt) vt = g_vtfb;
    const int b  = blockIdx.y;
    const int m0 = blockIdx.x << 7;
    const float* A = vt + (size_t)b * CHW_ + (size_t)m0 * 128;  // lda = 128
    const float* B = g_att + (size_t)b * 16384;                 // ldb = 128

    ACC_INIT(acc2);
    sgemm_block_core(A, 128, B, 128, 128, acc2, smem, smem + 4096);
    ACC_UNPACK(acc2, acc);

    const float g = __ldg(gamma);
    float* base = outw + (size_t)b * CHW_;
    const int tx = threadIdx.x & 15, ty = threadIdx.x >> 4;
    #pragma unroll
    for (int i = 0; i < 8; i++) {
        float* row = base + (size_t)(m0 + ty * 8 + i) * 128 + tx * 8;
        float4 v0 = {acc[i][0] * g, acc[i][1] * g, acc[i][2] * g, acc[i][3] * g};
        float4 v1 = {acc[i][4] * g, acc[i][5] * g, acc[i][6] * g, acc[i][7] * g};
        *(float4*)row       = v0;
        *(float4*)(row + 4) = v1;
    }
}

// ---------------- launch ---------------------------------------------------
extern "C" void kernel_launch(void* const* d_in, const int* in_sizes, int n_in,
                              void* d_out, int out_size)
{
    const float* x  = (const float*)d_in[0];
    const float* Wq = (const float*)d_in[1];
    const float* bq = (const float*)d_in[2];
    const float* Wk = (const float*)d_in[3];
    const float* bk = (const float*)d_in[4];
    const float* Wv = (const float*)d_in[5];
    const float* bv = (const float*)d_in[6];
    const float* gm = (const float*)d_in[7];
    float* out = (float*)d_out;

    const bool full = (out_size >= FULL_SIZE);
    float* outw = out;  // out_w is the first tuple element either way
    float* qw   = full ? out + OFF_QW    : nullptr;
    float* ktw  = full ? out + OFF_KW    : nullptr;
    float* vtw  = full ? out + OFF_VW    : nullptr;
    float* gmw  = full ? out + OFF_GAMMA : nullptr;
    float* attw = full ? out + OFF_ATT   : nullptr;

    conv_qkv_kernel<<<dim3(128, 6, 8), 256>>>(x, Wq, bq, Wk, bk, Wv, bv, qw);
    transpose_kv_kernel<<<dim3(512, 4, 32), dim3(32, 8)>>>(ktw, vtw);
    att_gemm_kernel<<<dim3(SPLITK_, 8), 256>>>(qw, ktw);
    softmax_kernel<<<dim3(4, 8), 256>>>(attw, gmw, gm);
    out_gemm_kernel<<<dim3(256, 8), 256>>>(vtw, outw, gm);
}

// round 7
// speedup vs baseline: 1.3185x; 1.3185x over previous
#include <cuda_runtime.h>
#include <cuda_bf16.h>
#include <cstdint>

// Problem constants
#define HW_     16384            // H*W = 128*128
#define CHW_    4194304          // C*H*W = 256*16384
#define NB_     8                // batch
#define JD_     32768            // C*H*W / W = 32768 (reshaped inner dim)
#define SPLITK_ 128              // split-K factor for logit GEMM
#define KCH_    256              // 32768 / 128

// Output chunk offsets (floats) for the concatenated tuple
// (out_w, x_Qw, x_Kw, x_Vw, gamma, att)
#define OFF_OUTW  0
#define OFF_QW    33554432
#define OFF_KW    67108864
#define OFF_VW    100663296
#define OFF_GAMMA 134217728
#define OFF_ATT   134217729
#define FULL_SIZE 134348801

// ---------------- device-global scratch (no allocations allowed) -----------
__device__ float g_kscr[(size_t)NB_ * CHW_];             // K conv, normal layout
__device__ float g_vscr[(size_t)NB_ * CHW_];             // V conv, normal layout
__device__ float g_psum[(size_t)NB_ * SPLITK_ * 16384];  // split-K partial logits
__device__ float g_att [(size_t)NB_ * 16384];            // softmax result
// fallback buffers in case d_out only holds out_w
__device__ float g_qfb [(size_t)NB_ * CHW_];
__device__ float g_ktfb[(size_t)NB_ * CHW_];
__device__ float g_vtfb[(size_t)NB_ * CHW_];

// ---------------- bf16 hi/lo split helpers ---------------------------------
__device__ __forceinline__ void split2(float x, float y, uint32_t& hi, uint32_t& lo) {
    __nv_bfloat16 hx = __float2bfloat16_rn(x);
    __nv_bfloat16 hy = __float2bfloat16_rn(y);
    __nv_bfloat162 h; h.x = hx; h.y = hy;                    // .x = low 16 bits
    hi = *reinterpret_cast<uint32_t*>(&h);
    __nv_bfloat162 l = __floats2bfloat162_rn(x - __bfloat162float(hx),
                                             y - __bfloat162float(hy));
    lo = *reinterpret_cast<uint32_t*>(&l);
}

// mma.sync m16n8k16 bf16 (baseline PTX, sm_80+) — fp32 accumulate in-place
__device__ __forceinline__ void mma16816(float* c, const uint32_t a[4],
                                         uint32_t b0, uint32_t b1) {
    asm("mma.sync.aligned.m16n8k16.row.col.f32.bf16.bf16.f32 "
        "{%0,%1,%2,%3}, {%4,%5,%6,%7}, {%8,%9}, {%0,%1,%2,%3};"
        : "+f"(c[0]), "+f"(c[1]), "+f"(c[2]), "+f"(c[3])
        : "r"(a[0]), "r"(a[1]), "r"(a[2]), "r"(a[3]), "r"(b0), "r"(b1));
}

// ---------------- shared 128x128 HMMA GEMM core -----------------------------
// C[128,128] = A[128,K] * B[K,128];  A row-major (lda), B source k-major (ldb).
// Staged per k16 chunk into smem as bf16 hi/lo planes:
//   sA (hi @0, lo @1536):  [m=128][k=16], row stride 12 u32 (24 bf16 = 48B)
//   sB (hi @3072, lo @4608): [n=128][k=16], same stride (transposed at staging)
// 256 threads = 8 warps in 4(m) x 2(n); warp tile 32x64 = 2x8 m16n8k16 frags.
// acc[im][jn][4] fp32. 3 MMA passes per frag-pair: AhBh + AlBh + AhBl.
__device__ __forceinline__ void hmma_gemm128(
    const float* __restrict__ Ag, int lda,
    const float* __restrict__ Bg, int ldb,
    int nChunks, float acc[2][8][4], uint32_t* sm)
{
    const int tid  = threadIdx.x;
    const int lane = tid & 31;
    const int w    = tid >> 5;
    const int g    = lane >> 2;      // 0..7
    const int t4   = lane & 3;       // 0..3
    const int wm   = w & 3;          // m block (32 rows)
    const int wn   = w >> 2;         // n block (64 cols)

    // staging indices
    const int saRow = tid >> 1;            // 0..127
    const int saSeg = (tid & 1) << 3;      // 0 or 8
    const int sbKp  = tid >> 5;            // 0..7 (k-pair)
    const int sbNq  = tid & 31;            // 0..31 (4 n each)

    #pragma unroll 1
    for (int ch = 0; ch < nChunks; ch++) {
        __syncthreads();
        // ---- stage A chunk: [128][16] hi/lo --------------------------------
        {
            const float* src = Ag + (size_t)saRow * lda + ch * 16 + saSeg;
            float4 f0 = *(const float4*)src;
            float4 f1 = *(const float4*)(src + 4);
            uint32_t h0, l0, h1, l1, h2, l2, h3, l3;
            split2(f0.x, f0.y, h0, l0);
            split2(f0.z, f0.w, h1, l1);
            split2(f1.x, f1.y, h2, l2);
            split2(f1.z, f1.w, h3, l3);
            uint32_t base = saRow * 12 + (saSeg >> 1);
            sm[base + 0] = h0; sm[base + 1] = h1;
            sm[base + 2] = h2; sm[base + 3] = h3;
            sm[1536 + base + 0] = l0; sm[1536 + base + 1] = l1;
            sm[1536 + base + 2] = l2; sm[1536 + base + 3] = l3;
        }
        // ---- stage B chunk transposed: source [k][n] -> smem [n][k] --------
        {
            const float* r0 = Bg + (size_t)(ch * 16 + 2 * sbKp) * ldb + sbNq * 4;
            float4 a = *(const float4*)r0;
            float4 c = *(const float4*)(r0 + ldb);
            #pragma unroll
            for (int e = 0; e < 4; e++) {
                float av = (&a.x)[e], cv = (&c.x)[e];
                uint32_t hp, lp;
                split2(av, cv, hp, lp);     // (k even, k odd) packed
                const int n = sbNq * 4 + e;
                sm[3072 + n * 12 + sbKp] = hp;
                sm[4608 + n * 12 + sbKp] = lp;
            }
        }
        __syncthreads();

        // ---- A fragments (hi & lo) ----------------------------------------
        uint32_t aH[2][4], aL[2][4];
        #pragma unroll
        for (int im = 0; im < 2; im++) {
            const int rb = wm * 32 + im * 16;
            aH[im][0] = sm[(rb + g    ) * 12 + t4];
            aH[im][1] = sm[(rb + g + 8) * 12 + t4];
            aH[im][2] = sm[(rb + g    ) * 12 + 4 + t4];
            aH[im][3] = sm[(rb + g + 8) * 12 + 4 + t4];
            aL[im][0] = sm[1536 + (rb + g    ) * 12 + t4];
            aL[im][1] = sm[1536 + (rb + g + 8) * 12 + t4];
            aL[im][2] = sm[1536 + (rb + g    ) * 12 + 4 + t4];
            aL[im][3] = sm[1536 + (rb + g + 8) * 12 + 4 + t4];
        }
        // ---- B fragments + MMAs -------------------------------------------
        #pragma unroll
        for (int jn = 0; jn < 8; jn++) {
            const int ncol = wn * 64 + jn * 8 + g;
            uint32_t bH0 = sm[3072 + ncol * 12 + t4];
            uint32_t bH1 = sm[3072 + ncol * 12 + 4 + t4];
            uint32_t bL0 = sm[4608 + ncol * 12 + t4];
            uint32_t bL1 = sm[4608 + ncol * 12 + 4 + t4];
            #pragma unroll
            for (int im = 0; im < 2; im++) {
                mma16816(acc[im][jn], aH[im], bH0, bH1);
                mma16816(acc[im][jn], aL[im], bH0, bH1);
                mma16816(acc[im][jn], aH[im], bL0, bL1);
            }
        }
    }
}

#define HACC_INIT(acc)                                         \
    float acc[2][8][4];                                        \
    _Pragma("unroll")                                          \
    for (int _i = 0; _i < 2; _i++)                             \
        _Pragma("unroll")                                      \
        for (int _j = 0; _j < 8; _j++)                         \
            _Pragma("unroll")                                  \
            for (int _e = 0; _e < 4; _e++) acc[_i][_j][_e] = 0.f;

// ---------------- kernel 1: fused QKV 1x1 conv + bias + ReLU ---------------
// grid (128, 6, 8): x = n-tile, y = (m-half | op*2), z = batch
__global__ __launch_bounds__(256, 2) void conv_qkv_kernel(
    const float* __restrict__ x,
    const float* __restrict__ Wq, const float* __restrict__ bq,
    const float* __restrict__ Wk, const float* __restrict__ bk,
    const float* __restrict__ Wv, const float* __restrict__ bv,
    float* __restrict__ qdst)
{
    __shared__ uint32_t sm[6144];
    if (!qdst) qdst = g_qfb;
    const int b  = blockIdx.z;
    const int op = blockIdx.y >> 1;
    const int m0 = (blockIdx.y & 1) << 7;
    const int n0 = blockIdx.x << 7;

    const float* Wsel = (op == 0) ? Wq : (op == 1) ? Wk : Wv;
    const float* bsel = (op == 0) ? bq : (op == 1) ? bk : bv;
    float*       dst  = ((op == 0) ? qdst : (op == 1) ? g_kscr : g_vscr)
                      + (size_t)b * CHW_;

    HACC_INIT(acc);
    hmma_gemm128(Wsel + (size_t)m0 * 256, 256,
                 x + (size_t)b * CHW_ + n0, HW_, 16, acc, sm);

    const int lane = threadIdx.x & 31, w = threadIdx.x >> 5;
    const int g = lane >> 2, t4 = lane & 3, wm = w & 3, wn = w >> 2;
    #pragma unroll
    for (int im = 0; im < 2; im++) {
        const int mb = m0 + wm * 32 + im * 16;
        const float bb0 = __ldg(bsel + mb + g);
        const float bb1 = __ldg(bsel + mb + g + 8);
        #pragma unroll
        for (int jn = 0; jn < 8; jn++) {
            const int n = n0 + wn * 64 + jn * 8 + t4 * 2;
            float2 v0 = { fmaxf(acc[im][jn][0] + bb0, 0.f),
                          fmaxf(acc[im][jn][1] + bb0, 0.f) };
            float2 v1 = { fmaxf(acc[im][jn][2] + bb1, 0.f),
                          fmaxf(acc[im][jn][3] + bb1, 0.f) };
            *(float2*)(dst + (size_t)(mb + g    ) * HW_ + n) = v0;
            *(float2*)(dst + (size_t)(mb + g + 8) * HW_ + n) = v1;
        }
    }
}

// ---------------- kernel 2: K/V layout transpose into x_Kw / x_Vw ----------
// in:  scr[b][c][p]   out: [b][j][i] with j = (c&1)*16384 + p, i = c>>1
// grid (512, 4, 32): x = p-tile, y = i-tile, z = (b<<2)|(par<<1)|kv
__global__ void transpose_kv_kernel(float* __restrict__ ktw, float* __restrict__ vtw)
{
    __shared__ float tile[32][33];
    if (!ktw) ktw = g_ktfb;
    if (!vtw) vtw = g_vtfb;
    const int z   = blockIdx.z;
    const int kv  = z & 1;
    const int par = (z >> 1) & 1;
    const int b   = z >> 2;
    const float* src = (kv ? g_vscr : g_kscr) + (size_t)b * CHW_;
    float*       dst = (kv ? vtw    : ktw   ) + (size_t)b * CHW_;
    const int p0 = blockIdx.x << 5, i0 = blockIdx.y << 5;
    const int tx = threadIdx.x, ty = threadIdx.y;
    #pragma unroll
    for (int r = 0; r < 4; r++) {
        const int ii = ty + r * 8;
        tile[ii][tx] = src[(size_t)(2 * (i0 + ii) + par) * HW_ + p0 + tx];
    }
    __syncthreads();
    #pragma unroll
    for (int r = 0; r < 4; r++) {
        const int pp = ty + r * 8;
        dst[(size_t)(par * 16384 + p0 + pp) * 128 + i0 + tx] = tile[tx][pp];
    }
}

// ---------------- kernel 3: split-K logit GEMM  att_raw = Qr * Kr^T --------
// grid (SPLITK_, 8): x = k-split s, y = batch. Partial [128x128] -> g_psum.
__global__ __launch_bounds__(256, 2) void att_gemm_kernel(
    const float* __restrict__ q, const float* __restrict__ kt)
{
    __shared__ uint32_t sm[6144];
    if (!q)  q  = g_qfb;
    if (!kt) kt = g_ktfb;
    const int s = blockIdx.x, b = blockIdx.y;

    HACC_INIT(acc);
    hmma_gemm128(q  + (size_t)b * CHW_ + (size_t)s * KCH_, JD_,
                 kt + (size_t)b * CHW_ + (size_t)s * KCH_ * 128, 128,
                 16, acc, sm);

    float* Cp = g_psum + ((size_t)b * SPLITK_ + s) * 16384;
    const int lane = threadIdx.x & 31, w = threadIdx.x >> 5;
    const int g = lane >> 2, t4 = lane & 3, wm = w & 3, wn = w >> 2;
    #pragma unroll
    for (int im = 0; im < 2; im++) {
        const int mb = wm * 32 + im * 16;
        #pragma unroll
        for (int jn = 0; jn < 8; jn++) {
            const int n = wn * 64 + jn * 8 + t4 * 2;
            *(float2*)(Cp + (size_t)(mb + g    ) * 128 + n) =
                make_float2(acc[im][jn][0], acc[im][jn][1]);
            *(float2*)(Cp + (size_t)(mb + g + 8) * 128 + n) =
                make_float2(acc[im][jn][2], acc[im][jn][3]);
        }
    }
}

// ---------------- kernel 4: Kahan split-K reduce + softmax over axis=1 -----
// grid (128, 8): x = i' (column), y = batch; 128 threads = i (row)
__global__ void softmax_kernel(float* __restrict__ attw,
                               float* __restrict__ gmw,
                               const float* __restrict__ gamma)
{
    const int b = blockIdx.y, ip = blockIdx.x, i = threadIdx.x;
    const float* base = g_psum + (size_t)b * SPLITK_ * 16384 + (size_t)i * 128 + ip;
    float s = 0.f, comp = 0.f;
    for (int t = 0; t < SPLITK_; t++) {
        float y = __fsub_rn(base[(size_t)t * 16384], comp);
        float u = __fadd_rn(s, y);
        comp = __fsub_rn(__fsub_rn(u, s), y);
        s = u;
    }
    __shared__ float red[128];
    red[i] = s;
    __syncthreads();
    for (int off = 64; off > 0; off >>= 1) {
        if (i < off) red[i] = fmaxf(red[i], red[i + off]);
        __syncthreads();
    }
    const float mx = red[0];
    __syncthreads();
    const float e = expf(s - mx);
    red[i] = e;
    __syncthreads();
    for (int off = 64; off > 0; off >>= 1) {
        if (i < off) red[i] += red[i + off];
        __syncthreads();
    }
    const float r = e / red[0];
    g_att[(size_t)b * 16384 + (size_t)i * 128 + ip] = r;
    if (attw) attw[(size_t)b * 16384 + (size_t)i * 128 + ip] = r;
    if (gmw && b == 0 && ip == 0 && i == 0) *gmw = __ldg(gamma);
}

// ---------------- kernel 5: out1 = x_Vw @ att, scaled by gamma -------------
// grid (256, 8): x = m-tile (of 32768), y = batch
__global__ __launch_bounds__(256, 2) void out_gemm_kernel(
    const float* __restrict__ vt, float* __restrict__ outw,
    const float* __restrict__ gamma)
{
    __shared__ uint32_t sm[6144];
    if (!vt) vt = g_vtfb;
    const int b  = blockIdx.y;
    const int m0 = blockIdx.x << 7;

    HACC_INIT(acc);
    hmma_gemm128(vt + (size_t)b * CHW_ + (size_t)m0 * 128, 128,
                 g_att + (size_t)b * 16384, 128, 8, acc, sm);

    const float gsc = __ldg(gamma);
    float* base = outw + (size_t)b * CHW_;
    const int lane = threadIdx.x & 31, w = threadIdx.x >> 5;
    const int g = lane >> 2, t4 = lane & 3, wm = w & 3, wn = w >> 2;
    #pragma unroll
    for (int im = 0; im < 2; im++) {
        const int mb = m0 + wm * 32 + im * 16;
        #pragma unroll
        for (int jn = 0; jn < 8; jn++) {
            const int n = wn * 64 + jn * 8 + t4 * 2;
            *(float2*)(base + (size_t)(mb + g    ) * 128 + n) =
                make_float2(acc[im][jn][0] * gsc, acc[im][jn][1] * gsc);
            *(float2*)(base + (size_t)(mb + g + 8) * 128 + n) =
                make_float2(acc[im][jn][2] * gsc, acc[im][jn][3] * gsc);
        }
    }
}

// ---------------- launch ---------------------------------------------------
extern "C" void kernel_launch(void* const* d_in, const int* in_sizes, int n_in,
                              void* d_out, int out_size)
{
    const float* x  = (const float*)d_in[0];
    const float* Wq = (const float*)d_in[1];
    const float* bq = (const float*)d_in[2];
    const float* Wk = (const float*)d_in[3];
    const float* bk = (const float*)d_in[4];
    const float* Wv = (const float*)d_in[5];
    const float* bv = (const float*)d_in[6];
    const float* gm = (const float*)d_in[7];
    float* out = (float*)d_out;

    const bool full = (out_size >= FULL_SIZE);
    float* outw = out;  // out_w is the first tuple element either way
    float* qw   = full ? out + OFF_QW    : nullptr;
    float* ktw  = full ? out + OFF_KW    : nullptr;
    float* vtw  = full ? out + OFF_VW    : nullptr;
    float* gmw  = full ? out + OFF_GAMMA : nullptr;
    float* attw = full ? out + OFF_ATT   : nullptr;

    conv_qkv_kernel<<<dim3(128, 6, 8), 256>>>(x, Wq, bq, Wk, bk, Wv, bv, qw);
    transpose_kv_kernel<<<dim3(512, 4, 32), dim3(32, 8)>>>(ktw, vtw);
    att_gemm_kernel<<<dim3(SPLITK_, 8), 256>>>(qw, ktw);
    softmax_kernel<<<dim3(128, 8), 128>>>(attw, gmw, gm);
    out_gemm_kernel<<<dim3(256, 8), 256>>>(vtw, outw, gm);
}